// round 13
// baseline (speedup 1.0000x reference)
#include <cuda_runtime.h>
#include <cuda_bf16.h>
#include <cstdint>

// Problem constants
#define NN 4
#define CC 64
#define HH 96
#define WW 96
#define PP (HH * WW)       // 9216
#define OO 1728            // 3*C*9
#define KTOT 2304          // 256*9

// Scratch (__device__ globals per alloc-free rule)
// Cat layout: [n][128 cpair][PP]
__device__ unsigned g_ch[(size_t)NN * 128 * PP];    // cat bf16-hi pairs
__device__ unsigned g_cl[(size_t)NN * 128 * PP];    // cat bf16-lo pairs
__device__ unsigned g_yh[(size_t)NN * PP * 32];     // y transposed bf16-hi pairs [n][px][kp]
__device__ unsigned g_yl[(size_t)NN * PP * 32];
__device__ unsigned g_w1h[OO * 32];                 // gen_w bf16 pairs, REORDERED o' = dil*576+tap*64+c
__device__ unsigned g_w1l[OO * 32];
__device__ float    g_b1[OO];                       // gen_b reordered to o'
__device__ unsigned g_wBh[16 * 9 * 8 * 64];         // fuse_w packed [chunk][tap][kp][co]
__device__ unsigned g_wBl[16 * 9 * 8 * 64];

// ---- bf16 split helpers ----
static __device__ __forceinline__ void bsplit(float v, unsigned short& h, unsigned short& l) {
    __nv_bfloat16 bh = __float2bfloat16_rn(v);
    float r = v - __bfloat162float(bh);
    __nv_bfloat16 bl = __float2bfloat16_rn(r);
    h = __bfloat16_as_ushort(bh);
    l = __bfloat16_as_ushort(bl);
}
static __device__ __forceinline__ unsigned pk(unsigned short lo, unsigned short hi) {
    return ((unsigned)hi << 16) | lo;
}
static __device__ __forceinline__ uint32_t smem_u32(const void* p) {
    uint32_t a;
    asm("{ .reg .u64 t; cvta.to.shared.u64 t, %1; cvt.u32.u64 %0, t; }" : "=r"(a) : "l"(p));
    return a;
}

// ---- warp mma m16n8k16 bf16 + ldmatrix + cp.async ----
static __device__ __forceinline__ void mma16816(
    float& d0, float& d1, float& d2, float& d3,
    uint32_t a0, uint32_t a1, uint32_t a2, uint32_t a3,
    uint32_t b0, uint32_t b1)
{
    asm volatile(
        "mma.sync.aligned.m16n8k16.row.col.f32.bf16.bf16.f32 "
        "{%0,%1,%2,%3}, {%4,%5,%6,%7}, {%8,%9}, {%0,%1,%2,%3};"
        : "+f"(d0), "+f"(d1), "+f"(d2), "+f"(d3)
        : "r"(a0), "r"(a1), "r"(a2), "r"(a3), "r"(b0), "r"(b1));
}
static __device__ __forceinline__ void ldsm_x4(
    uint32_t& a0, uint32_t& a1, uint32_t& a2, uint32_t& a3, uint32_t addr)
{
    asm volatile(
        "ldmatrix.sync.aligned.m8n8.x4.shared.b16 {%0,%1,%2,%3}, [%4];"
        : "=r"(a0), "=r"(a1), "=r"(a2), "=r"(a3) : "r"(addr));
}
static __device__ __forceinline__ void cp16(uint32_t dst, const void* src) {
    asm volatile("cp.async.cg.shared.global [%0], [%1], 16;"
                 :: "r"(dst), "l"(src) : "memory");
}
static __device__ __forceinline__ void cp4z(uint32_t dst, const void* src, uint32_t sz) {
    asm volatile("cp.async.ca.shared.global [%0], [%1], 4, %2;"
                 :: "r"(dst), "l"(src), "r"(sz) : "memory");
}

// ============================================================
// Merged prep kernel: 1080 CTAs of 256 threads.
// ============================================================
__global__ void __launch_bounds__(256) prep_all(
    const float* __restrict__ y, const float* __restrict__ gen_w,
    const float* __restrict__ gen_b, const float* __restrict__ fuse_w)
{
    __shared__ float s[64][65];
    const int bx = blockIdx.x;
    const int tid = threadIdx.x;

    if (bx < 576) {
        const int n  = bx / 144;
        const int p0 = (bx - n * 144) * 64;
#pragma unroll
        for (int pass = 0; pass < 16; pass++) {
            int fid = tid + pass * 256;
            int k = fid >> 6, px = fid & 63;
            s[k][px] = __ldg(y + ((size_t)n * 64 + k) * PP + p0 + px);
        }
        __syncthreads();
        const int px = tid >> 2, q = tid & 3;
        unsigned hb[8], lb[8];
#pragma unroll
        for (int j = 0; j < 8; j++) {
            int k = q * 16 + j * 2;
            unsigned short h0, l0, h1, l1;
            bsplit(s[k][px], h0, l0);
            bsplit(s[k + 1][px], h1, l1);
            hb[j] = pk(h0, h1);
            lb[j] = pk(l0, l1);
        }
        size_t base = ((size_t)n * PP + p0 + px) * 32 + q * 8;
        *(uint4*)(g_yh + base)     = make_uint4(hb[0], hb[1], hb[2], hb[3]);
        *(uint4*)(g_yh + base + 4) = make_uint4(hb[4], hb[5], hb[6], hb[7]);
        *(uint4*)(g_yl + base)     = make_uint4(lb[0], lb[1], lb[2], lb[3]);
        *(uint4*)(g_yl + base + 4) = make_uint4(lb[4], lb[5], lb[6], lb[7]);
    } else if (bx < 792) {
        int idx = (bx - 576) * 256 + tid;
        if (idx < OO * 32) {
            int op = idx >> 5, kp = idx & 31;
            int dil = op / 576;
            int rem = op - dil * 576;
            int tap = rem >> 6;
            int c   = rem & 63;
            int src = dil * 576 + c * 9 + tap;
            unsigned short h0, l0, h1, l1;
            bsplit(__ldg(gen_w + (size_t)src * 64 + 2 * kp), h0, l0);
            bsplit(__ldg(gen_w + (size_t)src * 64 + 2 * kp + 1), h1, l1);
            g_w1h[idx] = pk(h0, h1);
            g_w1l[idx] = pk(l0, l1);
            if (kp == 0) g_b1[op] = __ldg(gen_b + src);
        }
    } else {
        int idx = (bx - 792) * 256 + tid;
        if (idx < 16 * 9 * 8 * 64) {
            int co  = idx & 63;
            int kp  = (idx >> 6) & 7;
            int tap = (idx >> 9) % 9;
            int chunk = idx / (64 * 8 * 9);
            int k1 = (chunk * 16 + 2 * kp) * 9 + tap;
            unsigned short h0, l0, h1, l1;
            bsplit(__ldg(fuse_w + (size_t)co * KTOT + k1), h0, l0);
            bsplit(__ldg(fuse_w + (size_t)co * KTOT + k1 + 9), h1, l1);
            g_wBh[idx] = pk(h0, h1);
            g_wBl[idx] = pk(l0, l1);
        }
    }
}

// ============================================================
// FUSED stage1+2 (exact R12): per CTA = 128 px, 27 chunks.
// grid (72, NN), 256 thr. 4 B-buffers, 2-deep prefetch, 1 sync/chunk.
// ============================================================
#define F_AH 0
#define F_AL 18432
#define F_B0 36864
#define F_BSTG 18432
#define F_SM (36864 + 4 * 18432)    // 110592

__global__ void __launch_bounds__(256, 2) fused12(const float* __restrict__ x)
{
    extern __shared__ __align__(16) char sm[];
    const uint32_t sbase = smem_u32(sm);
    const int n  = blockIdx.y;
    const int p0 = blockIdx.x * 128;
    const int tid = threadIdx.x;
    const int warp = tid >> 5, lane = tid & 31;
    const int g = lane >> 2, t = lane & 3;
    const int wm = warp & 1, wn = warp >> 1;
    const int rsel = lane & 15;
    const int half16 = (lane >> 4) * 16;

    {
        const uint4* yh = (const uint4*)(g_yh + ((size_t)n * PP + p0) * 32);
        const uint4* yl = (const uint4*)(g_yl + ((size_t)n * PP + p0) * 32);
#pragma unroll
        for (int pass = 0; pass < 4; pass++) {
            int fid = tid + pass * 256;
            int r = fid >> 3, q = fid & 7;
            *(uint4*)(sm + F_AH + r * 144 + q * 16) = yh[r * 8 + q];
            *(uint4*)(sm + F_AL + r * 144 + q * 16) = yl[r * 8 + q];
        }
    }

    int hE[8], wE[8];
#pragma unroll
    for (int mi = 0; mi < 4; mi++)
#pragma unroll
        for (int r = 0; r < 2; r++) {
            int px = wm * 64 + mi * 16 + g + 8 * r;
            int p  = p0 + px;
            hE[mi * 2 + r] = p / WW;
            wE[mi * 2 + r] = p - (p / WW) * WW;
        }

#pragma unroll
    for (int mi = 0; mi < 4; mi++)
#pragma unroll
        for (int r = 0; r < 2; r++) {
            int px = wm * 64 + mi * 16 + g + 8 * r;
#pragma unroll
            for (int ni = 0; ni < 2; ni++) {
                int ce = wn * 16 + ni * 8 + 2 * t;
                float v0 = __ldg(x + ((size_t)n * CC + ce) * PP + p0 + px);
                float v1 = __ldg(x + ((size_t)n * CC + ce + 1) * PP + p0 + px);
                unsigned short he, le, ho, lo;
                bsplit(v0, he, le);
                bsplit(v1, ho, lo);
                int cpair = wn * 8 + ni * 4 + t;
                size_t gi = ((size_t)n * 128 + cpair) * PP + p0 + px;
                g_ch[gi] = pk(he, ho);
                g_cl[gi] = pk(le, lo);
            }
        }

    auto prefetch = [&](int ch) {
        const uint32_t so = F_B0 + (uint32_t)(ch & 3) * F_BSTG;
#pragma unroll
        for (int ps = 0; ps < 2; ps++) {
            int fid = tid + ps * 256;
            int o = fid >> 3, q = fid & 7;
            size_t gi = ((size_t)(ch * 64 + o)) * 32 + q * 4;
            uint32_t doff = sbase + so + (uint32_t)(o * 144 + q * 16);
            cp16(doff,        g_w1h + gi);
            cp16(doff + 9216, g_w1l + gi);
        }
        asm volatile("cp.async.commit_group;" ::: "memory");
    };

    prefetch(0);
    prefetch(1);
    __syncthreads();

    const float* xn = x + (size_t)n * CC * PP;

#pragma unroll 1
    for (int dil = 0; dil < 3; dil++) {
        float acc[4][2][4];
#pragma unroll
        for (int i = 0; i < 4; i++)
#pragma unroll
            for (int j = 0; j < 2; j++)
#pragma unroll
                for (int q = 0; q < 4; q++) acc[i][j][q] = 0.f;

        const int dd = 2 * dil + 1;

#pragma unroll 1
        for (int tap = 0; tap < 9; tap++) {
            const int ch = dil * 9 + tap;
            const uint32_t so = F_B0 + (uint32_t)(ch & 3) * F_BSTG;
            if (ch + 2 < 27) {
                prefetch(ch + 2);
                asm volatile("cp.async.wait_group 2;" ::: "memory");
            } else if (ch + 2 == 27) {
                asm volatile("cp.async.wait_group 1;" ::: "memory");
            } else {
                asm volatile("cp.async.wait_group 0;" ::: "memory");
            }
            __syncthreads();

            float d[4][2][4];
#pragma unroll
            for (int i = 0; i < 4; i++)
#pragma unroll
                for (int j = 0; j < 2; j++)
#pragma unroll
                    for (int q = 0; q < 4; q++) d[i][j][q] = 0.f;

            const char* BH = sm + so;
            const char* BL = sm + so + 9216;
#pragma unroll
            for (int ks = 0; ks < 4; ks++) {
                const int kb = ks * 32;
                uint32_t aH[4][4], aL[4][4], bH[2][2], bL[2][2];
#pragma unroll
                for (int mi = 0; mi < 4; mi++) {
                    ldsm_x4(aH[mi][0], aH[mi][1], aH[mi][2], aH[mi][3],
                            sbase + F_AH + (wm * 64 + mi * 16 + rsel) * 144 + kb + half16);
                    ldsm_x4(aL[mi][0], aL[mi][1], aL[mi][2], aL[mi][3],
                            sbase + F_AL + (wm * 64 + mi * 16 + rsel) * 144 + kb + half16);
                }
#pragma unroll
                for (int ni = 0; ni < 2; ni++) {
                    const char* pH = BH + (wn * 16 + ni * 8 + g) * 144 + kb + t * 4;
                    const char* pL = BL + (wn * 16 + ni * 8 + g) * 144 + kb + t * 4;
                    bH[ni][0] = *(const uint32_t*)pH;
                    bH[ni][1] = *(const uint32_t*)(pH + 16);
                    bL[ni][0] = *(const uint32_t*)pL;
                    bL[ni][1] = *(const uint32_t*)(pL + 16);
                }
#pragma unroll
                for (int mi = 0; mi < 4; mi++)
#pragma unroll
                    for (int ni = 0; ni < 2; ni++) {
                        mma16816(d[mi][ni][0], d[mi][ni][1], d[mi][ni][2], d[mi][ni][3],
                                 aH[mi][0], aH[mi][1], aH[mi][2], aH[mi][3],
                                 bH[ni][0], bH[ni][1]);
                        mma16816(d[mi][ni][0], d[mi][ni][1], d[mi][ni][2], d[mi][ni][3],
                                 aH[mi][0], aH[mi][1], aH[mi][2], aH[mi][3],
                                 bL[ni][0], bL[ni][1]);
                        mma16816(d[mi][ni][0], d[mi][ni][1], d[mi][ni][2], d[mi][ni][3],
                                 aL[mi][0], aL[mi][1], aL[mi][2], aL[mi][3],
                                 bH[ni][0], bH[ni][1]);
                    }
            }

            const int did = (tap / 3 - 1) * dd;
            const int djd = (tap % 3 - 1) * dd;
            const int soff = did * WW + djd;
            float2 bias[2];
#pragma unroll
            for (int ni = 0; ni < 2; ni++)
                bias[ni] = __ldg((const float2*)(g_b1 + ch * 64 + wn * 16 + ni * 8 + 2 * t));

#pragma unroll
            for (int mi = 0; mi < 4; mi++)
#pragma unroll
                for (int r = 0; r < 2; r++) {
                    const int e = mi * 2 + r;
                    const bool vok = ((unsigned)(hE[e] + did) < (unsigned)HH) &&
                                     ((unsigned)(wE[e] + djd) < (unsigned)WW);
                    const int px = wm * 64 + mi * 16 + g + 8 * r;
                    const int pa = p0 + px + soff;
#pragma unroll
                    for (int ni = 0; ni < 2; ni++) {
                        const int ce = wn * 16 + ni * 8 + 2 * t;
                        float x0 = 0.f, x1 = 0.f;
                        if (vok) {
                            x0 = __ldg(xn + (size_t)ce * PP + pa);
                            x1 = __ldg(xn + (size_t)(ce + 1) * PP + pa);
                        }
                        acc[mi][ni][r * 2 + 0] += (d[mi][ni][r * 2 + 0] + bias[ni].x) * x0;
                        acc[mi][ni][r * 2 + 1] += (d[mi][ni][r * 2 + 1] + bias[ni].y) * x1;
                    }
                }
        }

#pragma unroll
        for (int mi = 0; mi < 4; mi++)
#pragma unroll
            for (int r = 0; r < 2; r++) {
                int px = wm * 64 + mi * 16 + g + 8 * r;
#pragma unroll
                for (int ni = 0; ni < 2; ni++) {
                    unsigned short he, le, ho, lo;
                    bsplit(acc[mi][ni][r * 2 + 0], he, le);
                    bsplit(acc[mi][ni][r * 2 + 1], ho, lo);
                    int cpair = (dil + 1) * 32 + wn * 8 + ni * 4 + t;
                    size_t gi = ((size_t)n * 128 + cpair) * PP + p0 + px;
                    g_ch[gi] = pk(he, ho);
                    g_cl[gi] = pk(le, lo);
                }
            }
    }
}

// ============================================================
// Stage 3: CTA = 2 rows x 32 co, 256 thr, grid (48, 2, 4).
// A smem rows interleave H/L: [4 dy][100 px][8H | 8L | 4 pad] (80 B rows).
// 2 stages (55 KB each) -> 2 CTAs/SM = 16 warps/SM.
// One sync per chunk: wait -> sync -> prefetch(next) -> MMA.
// ============================================================
#define S3_BH_O  32000
#define S3_BL_O  43520
#define S3_STG   55040
#define S3_SM    (2 * S3_STG)     // 110080

__global__ void __launch_bounds__(256, 2) stage3_mma(
    const float* __restrict__ fuse_b, float* __restrict__ out)
{
    extern __shared__ __align__(16) char sm[];
    const uint32_t sbase = smem_u32(sm);
    const int h0  = blockIdx.x * 2;
    const int coh = blockIdx.y;
    const int n   = blockIdx.z;
    const int tid = threadIdx.x;
    const int warp = tid >> 5, lane = tid & 31;
    const int g = lane >> 2, t = lane & 3;
    const int r  = warp & 1;
    const int wm = (warp >> 1) & 1;
    const int wn = warp >> 2;
    const int rsel = lane & 15;
    const int half16 = (lane >> 4) * 16;

    auto prefetch = [&](int chunk, uint32_t so) {
        if (tid < 196) {
            const int rh = tid / 98;
            const int u  = tid - rh * 98;
            const int w  = u - 1;
            const bool wok = (unsigned)w < (unsigned)WW;
#pragma unroll
            for (int rr = 0; rr < 16; rr++) {
                int row = rh * 16 + rr;
                int dy = row >> 3, kpl = row & 7;
                int hh = h0 + dy - 1;
                uint32_t sz = (wok && (unsigned)hh < (unsigned)HH) ? 4u : 0u;
                size_t gi = ((size_t)n * 128 + chunk * 8 + kpl) * PP
                            + (sz ? (hh * WW + w) : 0);
                uint32_t doff = sbase + so + (uint32_t)(((dy * 100 + u) * 20 + kpl) * 4);
                cp4z(doff,      g_ch + gi, sz);
                cp4z(doff + 32, g_cl + gi, sz);
            }
        }
#pragma unroll
        for (int ps = 0; ps < 3; ps++) {
            int fid = tid + ps * 256;
            if (fid < 576) {
                int tapk = fid >> 3, q = fid & 7;
                size_t gi = ((size_t)chunk * 72 + tapk) * 64 + coh * 32 + q * 4;
                uint32_t doff = sbase + so + S3_BH_O + (uint32_t)((tapk * 40 + q * 4) * 4);
                cp16(doff,                       g_wBh + gi);
                cp16(doff + (S3_BL_O - S3_BH_O), g_wBl + gi);
            }
        }
        asm volatile("cp.async.commit_group;" ::: "memory");
    };

    float d[3][2][4];
#pragma unroll
    for (int i = 0; i < 3; i++)
#pragma unroll
        for (int j = 0; j < 2; j++)
#pragma unroll
            for (int q = 0; q < 4; q++) d[i][j][q] = 0.f;

    prefetch(0, 0);

    int cur = 0;
#pragma unroll 1
    for (int chunk = 0; chunk < 16; chunk++) {
        const uint32_t so = (uint32_t)cur * S3_STG;
        // wait for this chunk's data (the only outstanding group)
        asm volatile("cp.async.wait_group 0;" ::: "memory");
        __syncthreads();
        // prefetch next into the other buffer; safe: all warps finished the
        // previous chunk's MMAs before this sync.
        if (chunk + 1 < 16) prefetch(chunk + 1, (uint32_t)(cur ^ 1) * S3_STG);

#pragma unroll
        for (int s = 0; s < 3; s++) {
            const uint32_t Ab = sbase + so + ((s < 2) ? 0u : 32u)
                                + rsel * 80 + half16;
            const char* Bp = sm + so + ((s == 1) ? S3_BL_O : S3_BH_O);
#pragma unroll
            for (int tap = 0; tap < 9; tap++) {
                const int dy = tap / 3, dx = tap % 3;
                uint32_t b[2][2];
#pragma unroll
                for (int ni = 0; ni < 2; ni++) {
                    int coL = wn * 16 + ni * 8 + g;
                    b[ni][0] = *(const uint32_t*)(Bp + ((tap * 8 + t) * 40 + coL) * 4);
                    b[ni][1] = *(const uint32_t*)(Bp + ((tap * 8 + t + 4) * 40 + coL) * 4);
                }
#pragma unroll
                for (int mi = 0; mi < 3; mi++) {
                    int px0 = wm * 48 + mi * 16 + dx;
                    uint32_t a0, a1, a2, a3;
                    ldsm_x4(a0, a1, a2, a3, Ab + ((r + dy) * 100 + px0) * 80);
#pragma unroll
                    for (int ni = 0; ni < 2; ni++)
                        mma16816(d[mi][ni][0], d[mi][ni][1], d[mi][ni][2], d[mi][ni][3],
                                 a0, a1, a2, a3, b[ni][0], b[ni][1]);
                }
            }
        }
        cur ^= 1;
    }

    const int h = h0 + r;
#pragma unroll
    for (int mi = 0; mi < 3; mi++) {
        int pxcol = wm * 48 + mi * 16 + g;
#pragma unroll
        for (int ni = 0; ni < 2; ni++) {
            int co = coh * 32 + wn * 16 + ni * 8 + 2 * t;
            float b0v = __ldg(fuse_b + co);
            float b1v = __ldg(fuse_b + co + 1);
            float* r0 = out + ((size_t)n * CC + co) * PP + h * WW;
            float* r1 = r0 + PP;
            r0[pxcol]     = d[mi][ni][0] + b0v;
            r1[pxcol]     = d[mi][ni][1] + b1v;
            r0[pxcol + 8] = d[mi][ni][2] + b0v;
            r1[pxcol + 8] = d[mi][ni][3] + b1v;
        }
    }
}

// ============================================================
extern "C" void kernel_launch(void* const* d_in, const int* in_sizes, int n_in,
                              void* d_out, int out_size)
{
    (void)in_sizes; (void)n_in; (void)out_size;
    const float* x      = (const float*)d_in[0];
    const float* y      = (const float*)d_in[1];
    const float* gen_w  = (const float*)d_in[2];
    const float* gen_b  = (const float*)d_in[3];
    const float* fuse_w = (const float*)d_in[4];
    const float* fuse_b = (const float*)d_in[5];
    float* out = (float*)d_out;

    cudaFuncSetAttribute(fused12, cudaFuncAttributeMaxDynamicSharedMemorySize, F_SM);
    cudaFuncSetAttribute(stage3_mma, cudaFuncAttributeMaxDynamicSharedMemorySize, S3_SM);

    prep_all<<<1080, 256>>>(y, gen_w, gen_b, fuse_w);

    fused12<<<dim3(PP / 128, NN), 256, F_SM>>>(x);

    stage3_mma<<<dim3(HH / 2, 2, NN), 256, S3_SM>>>(fuse_b, out);
}

// round 14
// speedup vs baseline: 1.1785x; 1.1785x over previous
#include <cuda_runtime.h>
#include <cuda_bf16.h>
#include <cstdint>

// Problem constants
#define NN 4
#define CC 64
#define HH 96
#define WW 96
#define PP (HH * WW)       // 9216
#define OO 1728            // 3*C*9
#define KTOT 2304          // 256*9

// Scratch (__device__ globals per alloc-free rule)
// Cat layout: [n][128 cpair][PP]
__device__ unsigned g_ch[(size_t)NN * 128 * PP];    // cat bf16-hi pairs
__device__ unsigned g_cl[(size_t)NN * 128 * PP];    // cat bf16-lo pairs
__device__ unsigned g_w1h[OO * 32];                 // gen_w bf16 pairs, REORDERED o' = dil*576+tap*64+c
__device__ unsigned g_w1l[OO * 32];
__device__ float    g_b1[OO];                       // gen_b reordered to o'
__device__ unsigned g_wBh[16 * 9 * 8 * 64];         // fuse_w packed [chunk][tap][kp][co]
__device__ unsigned g_wBl[16 * 9 * 8 * 64];

// ---- bf16 split helpers ----
static __device__ __forceinline__ void bsplit(float v, unsigned short& h, unsigned short& l) {
    __nv_bfloat16 bh = __float2bfloat16_rn(v);
    float r = v - __bfloat162float(bh);
    __nv_bfloat16 bl = __float2bfloat16_rn(r);
    h = __bfloat16_as_ushort(bh);
    l = __bfloat16_as_ushort(bl);
}
static __device__ __forceinline__ unsigned pk(unsigned short lo, unsigned short hi) {
    return ((unsigned)hi << 16) | lo;
}
static __device__ __forceinline__ uint32_t smem_u32(const void* p) {
    uint32_t a;
    asm("{ .reg .u64 t; cvta.to.shared.u64 t, %1; cvt.u32.u64 %0, t; }" : "=r"(a) : "l"(p));
    return a;
}

// ---- warp mma m16n8k16 bf16 + ldmatrix + cp.async ----
static __device__ __forceinline__ void mma16816(
    float& d0, float& d1, float& d2, float& d3,
    uint32_t a0, uint32_t a1, uint32_t a2, uint32_t a3,
    uint32_t b0, uint32_t b1)
{
    asm volatile(
        "mma.sync.aligned.m16n8k16.row.col.f32.bf16.bf16.f32 "
        "{%0,%1,%2,%3}, {%4,%5,%6,%7}, {%8,%9}, {%0,%1,%2,%3};"
        : "+f"(d0), "+f"(d1), "+f"(d2), "+f"(d3)
        : "r"(a0), "r"(a1), "r"(a2), "r"(a3), "r"(b0), "r"(b1));
}
static __device__ __forceinline__ void ldsm_x4(
    uint32_t& a0, uint32_t& a1, uint32_t& a2, uint32_t& a3, uint32_t addr)
{
    asm volatile(
        "ldmatrix.sync.aligned.m8n8.x4.shared.b16 {%0,%1,%2,%3}, [%4];"
        : "=r"(a0), "=r"(a1), "=r"(a2), "=r"(a3) : "r"(addr));
}
static __device__ __forceinline__ void cp16(uint32_t dst, const void* src) {
    asm volatile("cp.async.cg.shared.global [%0], [%1], 16;"
                 :: "r"(dst), "l"(src) : "memory");
}
static __device__ __forceinline__ void cp4z(uint32_t dst, const void* src, uint32_t sz) {
    asm volatile("cp.async.ca.shared.global [%0], [%1], 4, %2;"
                 :: "r"(dst), "l"(src), "r"(sz) : "memory");
}

// ============================================================
// Merged prep kernel (weights only now): 504 CTAs of 256 threads.
//   bx < 216: prep_w1 ; else prep_w3 (288 blocks)
// ============================================================
__global__ void __launch_bounds__(256) prep_all(
    const float* __restrict__ gen_w, const float* __restrict__ gen_b,
    const float* __restrict__ fuse_w)
{
    const int bx = blockIdx.x;
    const int tid = threadIdx.x;

    if (bx < 216) {
        int idx = bx * 256 + tid;
        if (idx < OO * 32) {
            int op = idx >> 5, kp = idx & 31;
            int dil = op / 576;
            int rem = op - dil * 576;
            int tap = rem >> 6;
            int c   = rem & 63;
            int src = dil * 576 + c * 9 + tap;
            unsigned short h0, l0, h1, l1;
            bsplit(__ldg(gen_w + (size_t)src * 64 + 2 * kp), h0, l0);
            bsplit(__ldg(gen_w + (size_t)src * 64 + 2 * kp + 1), h1, l1);
            g_w1h[idx] = pk(h0, h1);
            g_w1l[idx] = pk(l0, l1);
            if (kp == 0) g_b1[op] = __ldg(gen_b + src);
        }
    } else {
        int idx = (bx - 216) * 256 + tid;
        if (idx < 16 * 9 * 8 * 64) {
            int co  = idx & 63;
            int kp  = (idx >> 6) & 7;
            int tap = (idx >> 9) % 9;
            int chunk = idx / (64 * 8 * 9);
            int k1 = (chunk * 16 + 2 * kp) * 9 + tap;
            unsigned short h0, l0, h1, l1;
            bsplit(__ldg(fuse_w + (size_t)co * KTOT + k1), h0, l0);
            bsplit(__ldg(fuse_w + (size_t)co * KTOT + k1 + 9), h1, l1);
            g_wBh[idx] = pk(h0, h1);
            g_wBl[idx] = pk(l0, l1);
        }
    }
}

// ============================================================
// FUSED stage1+2: per CTA = 128 px, 27 chunks. grid (72, NN), 256 thr.
// A-tile built in-kernel from y (staged transpose + bsplit).
// 4 B-buffers, 2-deep prefetch, 1 sync/chunk. (MMA path = R12.)
// ============================================================
#define F_AH 0
#define F_AL 18432
#define F_B0 36864
#define F_BSTG 18432
#define F_SM (36864 + 4 * 18432)    // 110592

__global__ void __launch_bounds__(256, 2) fused12(
    const float* __restrict__ x, const float* __restrict__ y)
{
    extern __shared__ __align__(16) char sm[];
    const uint32_t sbase = smem_u32(sm);
    const int n  = blockIdx.y;
    const int p0 = blockIdx.x * 128;
    const int tid = threadIdx.x;
    const int warp = tid >> 5, lane = tid & 31;
    const int g = lane >> 2, t = lane & 3;
    const int wm = warp & 1, wn = warp >> 1;
    const int rsel = lane & 15;
    const int half16 = (lane >> 4) * 16;

    // ---- build A (y^T, bf16 split) in-kernel ----
    {
        float* ystage = (float*)(sm + F_B0);   // [64][132] floats (33.8 KB, temp)
        // coalesced f32 loads: 2048 float4
#pragma unroll
        for (int pass = 0; pass < 8; pass++) {
            int fid = tid + pass * 256;        // 0..2047
            int k  = fid >> 5;
            int p4 = (fid & 31) * 4;
            *(float4*)&ystage[k * 132 + p4] =
                *(const float4*)(y + ((size_t)n * 64 + k) * PP + p0 + p4);
        }
        __syncthreads();
        // transpose + bsplit: thread handles (px=r, q) -> 8 k values = 1 uint4 H/L
#pragma unroll
        for (int pass = 0; pass < 4; pass++) {
            int fid = tid + pass * 256;        // 0..1023
            int r = fid >> 3, q = fid & 7;     // px row, uint4 column
            unsigned hv[4], lv[4];
#pragma unroll
            for (int i = 0; i < 4; i++) {
                int k = q * 8 + i * 2;         // pair (k, k+1), m = q*4+i
                unsigned short h0, l0, h1, l1;
                bsplit(ystage[k * 132 + r], h0, l0);
                bsplit(ystage[(k + 1) * 132 + r], h1, l1);
                hv[i] = pk(h0, h1);
                lv[i] = pk(l0, l1);
            }
            *(uint4*)(sm + F_AH + r * 144 + q * 16) = make_uint4(hv[0], hv[1], hv[2], hv[3]);
            *(uint4*)(sm + F_AL + r * 144 + q * 16) = make_uint4(lv[0], lv[1], lv[2], lv[3]);
        }
    }

    int hE[8], wE[8];
#pragma unroll
    for (int mi = 0; mi < 4; mi++)
#pragma unroll
        for (int r = 0; r < 2; r++) {
            int px = wm * 64 + mi * 16 + g + 8 * r;
            int p  = p0 + px;
            hE[mi * 2 + r] = p / WW;
            wE[mi * 2 + r] = p - (p / WW) * WW;
        }

    // ---- x passthrough section (sec 0, global-only) ----
#pragma unroll
    for (int mi = 0; mi < 4; mi++)
#pragma unroll
        for (int r = 0; r < 2; r++) {
            int px = wm * 64 + mi * 16 + g + 8 * r;
#pragma unroll
            for (int ni = 0; ni < 2; ni++) {
                int ce = wn * 16 + ni * 8 + 2 * t;
                float v0 = __ldg(x + ((size_t)n * CC + ce) * PP + p0 + px);
                float v1 = __ldg(x + ((size_t)n * CC + ce + 1) * PP + p0 + px);
                unsigned short he, le, ho, lo;
                bsplit(v0, he, le);
                bsplit(v1, ho, lo);
                int cpair = wn * 8 + ni * 4 + t;
                size_t gi = ((size_t)n * 128 + cpair) * PP + p0 + px;
                g_ch[gi] = pk(he, ho);
                g_cl[gi] = pk(le, lo);
            }
        }

    // ystage reads done by everyone before B prefetch overwrites F_B0
    __syncthreads();

    auto prefetch = [&](int ch) {
        const uint32_t so = F_B0 + (uint32_t)(ch & 3) * F_BSTG;
#pragma unroll
        for (int ps = 0; ps < 2; ps++) {
            int fid = tid + ps * 256;
            int o = fid >> 3, q = fid & 7;
            size_t gi = ((size_t)(ch * 64 + o)) * 32 + q * 4;
            uint32_t doff = sbase + so + (uint32_t)(o * 144 + q * 16);
            cp16(doff,        g_w1h + gi);
            cp16(doff + 9216, g_w1l + gi);
        }
        asm volatile("cp.async.commit_group;" ::: "memory");
    };

    prefetch(0);
    prefetch(1);

    const float* xn = x + (size_t)n * CC * PP;

#pragma unroll 1
    for (int dil = 0; dil < 3; dil++) {
        float acc[4][2][4];
#pragma unroll
        for (int i = 0; i < 4; i++)
#pragma unroll
            for (int j = 0; j < 2; j++)
#pragma unroll
                for (int q = 0; q < 4; q++) acc[i][j][q] = 0.f;

        const int dd = 2 * dil + 1;

#pragma unroll 1
        for (int tap = 0; tap < 9; tap++) {
            const int ch = dil * 9 + tap;
            const uint32_t so = F_B0 + (uint32_t)(ch & 3) * F_BSTG;
            if (ch + 2 < 27) {
                prefetch(ch + 2);
                asm volatile("cp.async.wait_group 2;" ::: "memory");
            } else if (ch + 2 == 27) {
                asm volatile("cp.async.wait_group 1;" ::: "memory");
            } else {
                asm volatile("cp.async.wait_group 0;" ::: "memory");
            }
            __syncthreads();

            float d[4][2][4];
#pragma unroll
            for (int i = 0; i < 4; i++)
#pragma unroll
                for (int j = 0; j < 2; j++)
#pragma unroll
                    for (int q = 0; q < 4; q++) d[i][j][q] = 0.f;

            const char* BH = sm + so;
            const char* BL = sm + so + 9216;
#pragma unroll
            for (int ks = 0; ks < 4; ks++) {
                const int kb = ks * 32;
                uint32_t aH[4][4], aL[4][4], bH[2][2], bL[2][2];
#pragma unroll
                for (int mi = 0; mi < 4; mi++) {
                    ldsm_x4(aH[mi][0], aH[mi][1], aH[mi][2], aH[mi][3],
                            sbase + F_AH + (wm * 64 + mi * 16 + rsel) * 144 + kb + half16);
                    ldsm_x4(aL[mi][0], aL[mi][1], aL[mi][2], aL[mi][3],
                            sbase + F_AL + (wm * 64 + mi * 16 + rsel) * 144 + kb + half16);
                }
#pragma unroll
                for (int ni = 0; ni < 2; ni++) {
                    const char* pH = BH + (wn * 16 + ni * 8 + g) * 144 + kb + t * 4;
                    const char* pL = BL + (wn * 16 + ni * 8 + g) * 144 + kb + t * 4;
                    bH[ni][0] = *(const uint32_t*)pH;
                    bH[ni][1] = *(const uint32_t*)(pH + 16);
                    bL[ni][0] = *(const uint32_t*)pL;
                    bL[ni][1] = *(const uint32_t*)(pL + 16);
                }
#pragma unroll
                for (int mi = 0; mi < 4; mi++)
#pragma unroll
                    for (int ni = 0; ni < 2; ni++) {
                        mma16816(d[mi][ni][0], d[mi][ni][1], d[mi][ni][2], d[mi][ni][3],
                                 aH[mi][0], aH[mi][1], aH[mi][2], aH[mi][3],
                                 bH[ni][0], bH[ni][1]);
                        mma16816(d[mi][ni][0], d[mi][ni][1], d[mi][ni][2], d[mi][ni][3],
                                 aH[mi][0], aH[mi][1], aH[mi][2], aH[mi][3],
                                 bL[ni][0], bL[ni][1]);
                        mma16816(d[mi][ni][0], d[mi][ni][1], d[mi][ni][2], d[mi][ni][3],
                                 aL[mi][0], aL[mi][1], aL[mi][2], aL[mi][3],
                                 bH[ni][0], bH[ni][1]);
                    }
            }

            const int did = (tap / 3 - 1) * dd;
            const int djd = (tap % 3 - 1) * dd;
            const int soff = did * WW + djd;
            float2 bias[2];
#pragma unroll
            for (int ni = 0; ni < 2; ni++)
                bias[ni] = __ldg((const float2*)(g_b1 + ch * 64 + wn * 16 + ni * 8 + 2 * t));

#pragma unroll
            for (int mi = 0; mi < 4; mi++)
#pragma unroll
                for (int r = 0; r < 2; r++) {
                    const int e = mi * 2 + r;
                    const bool vok = ((unsigned)(hE[e] + did) < (unsigned)HH) &&
                                     ((unsigned)(wE[e] + djd) < (unsigned)WW);
                    const int px = wm * 64 + mi * 16 + g + 8 * r;
                    const int pa = p0 + px + soff;
#pragma unroll
                    for (int ni = 0; ni < 2; ni++) {
                        const int ce = wn * 16 + ni * 8 + 2 * t;
                        float x0 = 0.f, x1 = 0.f;
                        if (vok) {
                            x0 = __ldg(xn + (size_t)ce * PP + pa);
                            x1 = __ldg(xn + (size_t)(ce + 1) * PP + pa);
                        }
                        acc[mi][ni][r * 2 + 0] += (d[mi][ni][r * 2 + 0] + bias[ni].x) * x0;
                        acc[mi][ni][r * 2 + 1] += (d[mi][ni][r * 2 + 1] + bias[ni].y) * x1;
                    }
                }
        }

        // ---- write cat section (dil+1) ----
#pragma unroll
        for (int mi = 0; mi < 4; mi++)
#pragma unroll
            for (int r = 0; r < 2; r++) {
                int px = wm * 64 + mi * 16 + g + 8 * r;
#pragma unroll
                for (int ni = 0; ni < 2; ni++) {
                    unsigned short he, le, ho, lo;
                    bsplit(acc[mi][ni][r * 2 + 0], he, le);
                    bsplit(acc[mi][ni][r * 2 + 1], ho, lo);
                    int cpair = (dil + 1) * 32 + wn * 8 + ni * 4 + t;
                    size_t gi = ((size_t)n * 128 + cpair) * PP + p0 + px;
                    g_ch[gi] = pk(he, ho);
                    g_cl[gi] = pk(le, lo);
                }
            }
    }
}

// ============================================================
// Stage 3 (exact R12 best): CTA = 2 rows x 32 co, 256 thr, grid (48,2,4).
// 3 buffers, 1-deep prefetch, ONE sync per chunk.
// ============================================================
#define S3_AH    0
#define S3_AL_O  19200
#define S3_BH_O  38400
#define S3_BL_O  49920
#define S3_STG   61440
#define S3_SM    (3 * S3_STG)     // 184320

__global__ void __launch_bounds__(256) stage3_mma(
    const float* __restrict__ fuse_b, float* __restrict__ out)
{
    extern __shared__ __align__(16) char sm[];
    const uint32_t sbase = smem_u32(sm);
    const int h0  = blockIdx.x * 2;
    const int coh = blockIdx.y;
    const int n   = blockIdx.z;
    const int tid = threadIdx.x;
    const int warp = tid >> 5, lane = tid & 31;
    const int g = lane >> 2, t = lane & 3;
    const int r  = warp & 1;
    const int wm = (warp >> 1) & 1;
    const int wn = warp >> 2;
    const int rsel = lane & 15;
    const int half16 = (lane >> 4) * 16;

    auto prefetch = [&](int chunk, uint32_t so) {
        if (tid < 196) {
            const int rh = tid / 98;
            const int u  = tid - rh * 98;
            const int w  = u - 1;
            const bool wok = (unsigned)w < (unsigned)WW;
#pragma unroll
            for (int rr = 0; rr < 16; rr++) {
                int row = rh * 16 + rr;
                int dy = row >> 3, kpl = row & 7;
                int hh = h0 + dy - 1;
                uint32_t sz = (wok && (unsigned)hh < (unsigned)HH) ? 4u : 0u;
                size_t gi = ((size_t)n * 128 + chunk * 8 + kpl) * PP
                            + (sz ? (hh * WW + w) : 0);
                uint32_t doff = sbase + so + (uint32_t)(((dy * 100 + u) * 12 + kpl) * 4);
                cp4z(doff,           g_ch + gi, sz);
                cp4z(doff + S3_AL_O, g_cl + gi, sz);
            }
        }
#pragma unroll
        for (int ps = 0; ps < 3; ps++) {
            int fid = tid + ps * 256;
            if (fid < 576) {
                int tapk = fid >> 3, q = fid & 7;
                size_t gi = ((size_t)chunk * 72 + tapk) * 64 + coh * 32 + q * 4;
                uint32_t doff = sbase + so + S3_BH_O + (uint32_t)((tapk * 40 + q * 4) * 4);
                cp16(doff,                       g_wBh + gi);
                cp16(doff + (S3_BL_O - S3_BH_O), g_wBl + gi);
            }
        }
        asm volatile("cp.async.commit_group;" ::: "memory");
    };

    float d[3][2][4];
#pragma unroll
    for (int i = 0; i < 3; i++)
#pragma unroll
        for (int j = 0; j < 2; j++)
#pragma unroll
            for (int q = 0; q < 4; q++) d[i][j][q] = 0.f;

    prefetch(0, 0);

    int cur = 0;
#pragma unroll 1
    for (int chunk = 0; chunk < 16; chunk++) {
        const uint32_t so = (uint32_t)cur * S3_STG;
        int nxt = (cur == 2) ? 0 : cur + 1;
        if (chunk + 1 < 16) {
            prefetch(chunk + 1, (uint32_t)nxt * S3_STG);
            asm volatile("cp.async.wait_group 1;" ::: "memory");
        } else {
            asm volatile("cp.async.wait_group 0;" ::: "memory");
        }
        __syncthreads();

#pragma unroll
        for (int s = 0; s < 3; s++) {
            const uint32_t Ab = sbase + so + ((s < 2) ? 0u : (uint32_t)S3_AL_O)
                                + rsel * 48 + half16;
            const char* Bp = sm + so + ((s == 1) ? S3_BL_O : S3_BH_O);
#pragma unroll
            for (int tap = 0; tap < 9; tap++) {
                const int dy = tap / 3, dx = tap % 3;
                uint32_t b[2][2];
#pragma unroll
                for (int ni = 0; ni < 2; ni++) {
                    int coL = wn * 16 + ni * 8 + g;
                    b[ni][0] = *(const uint32_t*)(Bp + ((tap * 8 + t) * 40 + coL) * 4);
                    b[ni][1] = *(const uint32_t*)(Bp + ((tap * 8 + t + 4) * 40 + coL) * 4);
                }
#pragma unroll
                for (int mi = 0; mi < 3; mi++) {
                    int px0 = wm * 48 + mi * 16 + dx;
                    uint32_t a0, a1, a2, a3;
                    ldsm_x4(a0, a1, a2, a3, Ab + ((r + dy) * 100 + px0) * 48);
#pragma unroll
                    for (int ni = 0; ni < 2; ni++)
                        mma16816(d[mi][ni][0], d[mi][ni][1], d[mi][ni][2], d[mi][ni][3],
                                 a0, a1, a2, a3, b[ni][0], b[ni][1]);
                }
            }
        }
        cur = nxt;
    }

    const int h = h0 + r;
#pragma unroll
    for (int mi = 0; mi < 3; mi++) {
        int pxcol = wm * 48 + mi * 16 + g;
#pragma unroll
        for (int ni = 0; ni < 2; ni++) {
            int co = coh * 32 + wn * 16 + ni * 8 + 2 * t;
            float b0v = __ldg(fuse_b + co);
            float b1v = __ldg(fuse_b + co + 1);
            float* r0 = out + ((size_t)n * CC + co) * PP + h * WW;
            float* r1 = r0 + PP;
            r0[pxcol]     = d[mi][ni][0] + b0v;
            r1[pxcol]     = d[mi][ni][1] + b1v;
            r0[pxcol + 8] = d[mi][ni][2] + b0v;
            r1[pxcol + 8] = d[mi][ni][3] + b1v;
        }
    }
}

// ============================================================
extern "C" void kernel_launch(void* const* d_in, const int* in_sizes, int n_in,
                              void* d_out, int out_size)
{
    (void)in_sizes; (void)n_in; (void)out_size;
    const float* x      = (const float*)d_in[0];
    const float* y      = (const float*)d_in[1];
    const float* gen_w  = (const float*)d_in[2];
    const float* gen_b  = (const float*)d_in[3];
    const float* fuse_w = (const float*)d_in[4];
    const float* fuse_b = (const float*)d_in[5];
    float* out = (float*)d_out;

    cudaFuncSetAttribute(fused12, cudaFuncAttributeMaxDynamicSharedMemorySize, F_SM);
    cudaFuncSetAttribute(stage3_mma, cudaFuncAttributeMaxDynamicSharedMemorySize, S3_SM);

    prep_all<<<504, 256>>>(gen_w, gen_b, fuse_w);

    fused12<<<dim3(PP / 128, NN), 256, F_SM>>>(x, y);

    stage3_mma<<<dim3(HH / 2, 2, NN), 256, S3_SM>>>(fuse_b, out);
}

// round 15
// speedup vs baseline: 1.2632x; 1.0719x over previous
#include <cuda_runtime.h>
#include <cuda_bf16.h>
#include <cstdint>

// Problem constants
#define NN 4
#define CC 64
#define HH 96
#define WW 96
#define PP (HH * WW)       // 9216
#define OO 1728            // 3*C*9
#define KTOT 2304          // 256*9

// Scratch (__device__ globals per alloc-free rule)
// Cat layout: [n][128 cpair][PP]
__device__ unsigned g_ch[(size_t)NN * 128 * PP];    // cat bf16-hi pairs
__device__ unsigned g_cl[(size_t)NN * 128 * PP];    // cat bf16-lo pairs
__device__ unsigned g_w1h[OO * 32];                 // gen_w bf16 pairs, REORDERED o' = dil*576+tap*64+c
__device__ unsigned g_w1l[OO * 32];
__device__ float    g_b1[OO];                       // gen_b reordered to o'
__device__ unsigned g_wBh[16 * 9 * 8 * 64];         // fuse_w packed [chunk][tap][kp][co]
__device__ unsigned g_wBl[16 * 9 * 8 * 64];

// ---- bf16 split helpers ----
static __device__ __forceinline__ void bsplit(float v, unsigned short& h, unsigned short& l) {
    __nv_bfloat16 bh = __float2bfloat16_rn(v);
    float r = v - __bfloat162float(bh);
    __nv_bfloat16 bl = __float2bfloat16_rn(r);
    h = __bfloat16_as_ushort(bh);
    l = __bfloat16_as_ushort(bl);
}
static __device__ __forceinline__ unsigned pk(unsigned short lo, unsigned short hi) {
    return ((unsigned)hi << 16) | lo;
}
static __device__ __forceinline__ uint32_t smem_u32(const void* p) {
    uint32_t a;
    asm("{ .reg .u64 t; cvta.to.shared.u64 t, %1; cvt.u32.u64 %0, t; }" : "=r"(a) : "l"(p));
    return a;
}

// ---- warp mma m16n8k16 bf16 + ldmatrix + cp.async ----
static __device__ __forceinline__ void mma16816(
    float& d0, float& d1, float& d2, float& d3,
    uint32_t a0, uint32_t a1, uint32_t a2, uint32_t a3,
    uint32_t b0, uint32_t b1)
{
    asm volatile(
        "mma.sync.aligned.m16n8k16.row.col.f32.bf16.bf16.f32 "
        "{%0,%1,%2,%3}, {%4,%5,%6,%7}, {%8,%9}, {%0,%1,%2,%3};"
        : "+f"(d0), "+f"(d1), "+f"(d2), "+f"(d3)
        : "r"(a0), "r"(a1), "r"(a2), "r"(a3), "r"(b0), "r"(b1));
}
static __device__ __forceinline__ void ldsm_x4(
    uint32_t& a0, uint32_t& a1, uint32_t& a2, uint32_t& a3, uint32_t addr)
{
    asm volatile(
        "ldmatrix.sync.aligned.m8n8.x4.shared.b16 {%0,%1,%2,%3}, [%4];"
        : "=r"(a0), "=r"(a1), "=r"(a2), "=r"(a3) : "r"(addr));
}
static __device__ __forceinline__ void cp16(uint32_t dst, const void* src) {
    asm volatile("cp.async.cg.shared.global [%0], [%1], 16;"
                 :: "r"(dst), "l"(src) : "memory");
}
static __device__ __forceinline__ void cp4z(uint32_t dst, const void* src, uint32_t sz) {
    asm volatile("cp.async.ca.shared.global [%0], [%1], 4, %2;"
                 :: "r"(dst), "l"(src), "r"(sz) : "memory");
}

// ============================================================
// Merged prep kernel (weights only): 504 CTAs of 256 threads.
// ============================================================
__global__ void __launch_bounds__(256) prep_all(
    const float* __restrict__ gen_w, const float* __restrict__ gen_b,
    const float* __restrict__ fuse_w)
{
    const int bx = blockIdx.x;
    const int tid = threadIdx.x;

    if (bx < 216) {
        int idx = bx * 256 + tid;
        if (idx < OO * 32) {
            int op = idx >> 5, kp = idx & 31;
            int dil = op / 576;
            int rem = op - dil * 576;
            int tap = rem >> 6;
            int c   = rem & 63;
            int src = dil * 576 + c * 9 + tap;
            unsigned short h0, l0, h1, l1;
            bsplit(__ldg(gen_w + (size_t)src * 64 + 2 * kp), h0, l0);
            bsplit(__ldg(gen_w + (size_t)src * 64 + 2 * kp + 1), h1, l1);
            g_w1h[idx] = pk(h0, h1);
            g_w1l[idx] = pk(l0, l1);
            if (kp == 0) g_b1[op] = __ldg(gen_b + src);
        }
    } else {
        int idx = (bx - 216) * 256 + tid;
        if (idx < 16 * 9 * 8 * 64) {
            int co  = idx & 63;
            int kp  = (idx >> 6) & 7;
            int tap = (idx >> 9) % 9;
            int chunk = idx / (64 * 8 * 9);
            int k1 = (chunk * 16 + 2 * kp) * 9 + tap;
            unsigned short h0, l0, h1, l1;
            bsplit(__ldg(fuse_w + (size_t)co * KTOT + k1), h0, l0);
            bsplit(__ldg(fuse_w + (size_t)co * KTOT + k1 + 9), h1, l1);
            g_wBh[idx] = pk(h0, h1);
            g_wBl[idx] = pk(l0, l1);
        }
    }
}

// ============================================================
// FUSED stage1+2: per CTA = 128 px, 27 chunks. grid (72, NN), 256 thr.
// A-tile built in-kernel from y. 4 B-buffers, 2-deep prefetch, 1 sync/chunk.
// MMA emission order: splits outer (dependent-MMA distance 8).
// ============================================================
#define F_AH 0
#define F_AL 18432
#define F_B0 36864
#define F_BSTG 18432
#define F_SM (36864 + 4 * 18432)    // 110592

__global__ void __launch_bounds__(256, 2) fused12(
    const float* __restrict__ x, const float* __restrict__ y)
{
    extern __shared__ __align__(16) char sm[];
    const uint32_t sbase = smem_u32(sm);
    const int n  = blockIdx.y;
    const int p0 = blockIdx.x * 128;
    const int tid = threadIdx.x;
    const int warp = tid >> 5, lane = tid & 31;
    const int g = lane >> 2, t = lane & 3;
    const int wm = warp & 1, wn = warp >> 1;
    const int rsel = lane & 15;
    const int half16 = (lane >> 4) * 16;

    // ---- build A (y^T, bf16 split) in-kernel ----
    {
        float* ystage = (float*)(sm + F_B0);   // [64][132] floats (temp)
#pragma unroll
        for (int pass = 0; pass < 8; pass++) {
            int fid = tid + pass * 256;        // 0..2047
            int k  = fid >> 5;
            int p4 = (fid & 31) * 4;
            *(float4*)&ystage[k * 132 + p4] =
                *(const float4*)(y + ((size_t)n * 64 + k) * PP + p0 + p4);
        }
        __syncthreads();
#pragma unroll
        for (int pass = 0; pass < 4; pass++) {
            int fid = tid + pass * 256;        // 0..1023
            int r = fid >> 3, q = fid & 7;
            unsigned hv[4], lv[4];
#pragma unroll
            for (int i = 0; i < 4; i++) {
                int k = q * 8 + i * 2;
                unsigned short h0, l0, h1, l1;
                bsplit(ystage[k * 132 + r], h0, l0);
                bsplit(ystage[(k + 1) * 132 + r], h1, l1);
                hv[i] = pk(h0, h1);
                lv[i] = pk(l0, l1);
            }
            *(uint4*)(sm + F_AH + r * 144 + q * 16) = make_uint4(hv[0], hv[1], hv[2], hv[3]);
            *(uint4*)(sm + F_AL + r * 144 + q * 16) = make_uint4(lv[0], lv[1], lv[2], lv[3]);
        }
    }

    int hE[8], wE[8];
#pragma unroll
    for (int mi = 0; mi < 4; mi++)
#pragma unroll
        for (int r = 0; r < 2; r++) {
            int px = wm * 64 + mi * 16 + g + 8 * r;
            int p  = p0 + px;
            hE[mi * 2 + r] = p / WW;
            wE[mi * 2 + r] = p - (p / WW) * WW;
        }

    // ---- x passthrough section (sec 0) ----
#pragma unroll
    for (int mi = 0; mi < 4; mi++)
#pragma unroll
        for (int r = 0; r < 2; r++) {
            int px = wm * 64 + mi * 16 + g + 8 * r;
#pragma unroll
            for (int ni = 0; ni < 2; ni++) {
                int ce = wn * 16 + ni * 8 + 2 * t;
                float v0 = __ldg(x + ((size_t)n * CC + ce) * PP + p0 + px);
                float v1 = __ldg(x + ((size_t)n * CC + ce + 1) * PP + p0 + px);
                unsigned short he, le, ho, lo;
                bsplit(v0, he, le);
                bsplit(v1, ho, lo);
                int cpair = wn * 8 + ni * 4 + t;
                size_t gi = ((size_t)n * 128 + cpair) * PP + p0 + px;
                g_ch[gi] = pk(he, ho);
                g_cl[gi] = pk(le, lo);
            }
        }

    __syncthreads();   // ystage reads done before B prefetch overwrites F_B0

    auto prefetch = [&](int ch) {
        const uint32_t so = F_B0 + (uint32_t)(ch & 3) * F_BSTG;
#pragma unroll
        for (int ps = 0; ps < 2; ps++) {
            int fid = tid + ps * 256;
            int o = fid >> 3, q = fid & 7;
            size_t gi = ((size_t)(ch * 64 + o)) * 32 + q * 4;
            uint32_t doff = sbase + so + (uint32_t)(o * 144 + q * 16);
            cp16(doff,        g_w1h + gi);
            cp16(doff + 9216, g_w1l + gi);
        }
        asm volatile("cp.async.commit_group;" ::: "memory");
    };

    prefetch(0);
    prefetch(1);

    const float* xn = x + (size_t)n * CC * PP;

#pragma unroll 1
    for (int dil = 0; dil < 3; dil++) {
        float acc[4][2][4];
#pragma unroll
        for (int i = 0; i < 4; i++)
#pragma unroll
            for (int j = 0; j < 2; j++)
#pragma unroll
                for (int q = 0; q < 4; q++) acc[i][j][q] = 0.f;

        const int dd = 2 * dil + 1;

#pragma unroll 1
        for (int tap = 0; tap < 9; tap++) {
            const int ch = dil * 9 + tap;
            const uint32_t so = F_B0 + (uint32_t)(ch & 3) * F_BSTG;
            if (ch + 2 < 27) {
                prefetch(ch + 2);
                asm volatile("cp.async.wait_group 2;" ::: "memory");
            } else if (ch + 2 == 27) {
                asm volatile("cp.async.wait_group 1;" ::: "memory");
            } else {
                asm volatile("cp.async.wait_group 0;" ::: "memory");
            }
            __syncthreads();

            float d[4][2][4];
#pragma unroll
            for (int i = 0; i < 4; i++)
#pragma unroll
                for (int j = 0; j < 2; j++)
#pragma unroll
                    for (int q = 0; q < 4; q++) d[i][j][q] = 0.f;

            const char* BH = sm + so;
            const char* BL = sm + so + 9216;
#pragma unroll
            for (int ks = 0; ks < 4; ks++) {
                const int kb = ks * 32;
                uint32_t aH[4][4], aL[4][4], bH[2][2], bL[2][2];
#pragma unroll
                for (int mi = 0; mi < 4; mi++) {
                    ldsm_x4(aH[mi][0], aH[mi][1], aH[mi][2], aH[mi][3],
                            sbase + F_AH + (wm * 64 + mi * 16 + rsel) * 144 + kb + half16);
                    ldsm_x4(aL[mi][0], aL[mi][1], aL[mi][2], aL[mi][3],
                            sbase + F_AL + (wm * 64 + mi * 16 + rsel) * 144 + kb + half16);
                }
#pragma unroll
                for (int ni = 0; ni < 2; ni++) {
                    const char* pH = BH + (wn * 16 + ni * 8 + g) * 144 + kb + t * 4;
                    const char* pL = BL + (wn * 16 + ni * 8 + g) * 144 + kb + t * 4;
                    bH[ni][0] = *(const uint32_t*)pH;
                    bH[ni][1] = *(const uint32_t*)(pH + 16);
                    bL[ni][0] = *(const uint32_t*)pL;
                    bL[ni][1] = *(const uint32_t*)(pL + 16);
                }
                // splits outermost: dependent-MMA distance = 8
#pragma unroll
                for (int s = 0; s < 3; s++)
#pragma unroll
                    for (int mi = 0; mi < 4; mi++)
#pragma unroll
                        for (int ni = 0; ni < 2; ni++) {
                            const uint32_t* a = (s < 2) ? aH[mi] : aL[mi];
                            const uint32_t* b = (s == 1) ? bL[ni] : bH[ni];
                            mma16816(d[mi][ni][0], d[mi][ni][1], d[mi][ni][2], d[mi][ni][3],
                                     a[0], a[1], a[2], a[3], b[0], b[1]);
                        }
            }

            const int did = (tap / 3 - 1) * dd;
            const int djd = (tap % 3 - 1) * dd;
            const int soff = did * WW + djd;
            float2 bias[2];
#pragma unroll
            for (int ni = 0; ni < 2; ni++)
                bias[ni] = __ldg((const float2*)(g_b1 + ch * 64 + wn * 16 + ni * 8 + 2 * t));

#pragma unroll
            for (int mi = 0; mi < 4; mi++)
#pragma unroll
                for (int r = 0; r < 2; r++) {
                    const int e = mi * 2 + r;
                    const bool vok = ((unsigned)(hE[e] + did) < (unsigned)HH) &&
                                     ((unsigned)(wE[e] + djd) < (unsigned)WW);
                    const int px = wm * 64 + mi * 16 + g + 8 * r;
                    const int pa = p0 + px + soff;
#pragma unroll
                    for (int ni = 0; ni < 2; ni++) {
                        const int ce = wn * 16 + ni * 8 + 2 * t;
                        float x0 = 0.f, x1 = 0.f;
                        if (vok) {
                            x0 = __ldg(xn + (size_t)ce * PP + pa);
                            x1 = __ldg(xn + (size_t)(ce + 1) * PP + pa);
                        }
                        acc[mi][ni][r * 2 + 0] += (d[mi][ni][r * 2 + 0] + bias[ni].x) * x0;
                        acc[mi][ni][r * 2 + 1] += (d[mi][ni][r * 2 + 1] + bias[ni].y) * x1;
                    }
                }
        }

        // ---- write cat section (dil+1) ----
#pragma unroll
        for (int mi = 0; mi < 4; mi++)
#pragma unroll
            for (int r = 0; r < 2; r++) {
                int px = wm * 64 + mi * 16 + g + 8 * r;
#pragma unroll
                for (int ni = 0; ni < 2; ni++) {
                    unsigned short he, le, ho, lo;
                    bsplit(acc[mi][ni][r * 2 + 0], he, le);
                    bsplit(acc[mi][ni][r * 2 + 1], ho, lo);
                    int cpair = (dil + 1) * 32 + wn * 8 + ni * 4 + t;
                    size_t gi = ((size_t)n * 128 + cpair) * PP + p0 + px;
                    g_ch[gi] = pk(he, ho);
                    g_cl[gi] = pk(le, lo);
                }
            }
    }
}

// ============================================================
// Stage 3: CTA = 2 rows x 32 co, 256 thr, grid (48,2,4).
// 3 buffers, 1-deep prefetch, ONE sync per chunk.
// Single tap pass; 3 accumulator sets (per split) -> dependent-MMA
// distance 18; aH reused for 2 splits (fewer LDSM/LDS).
// ============================================================
#define S3_AH    0
#define S3_AL_O  19200
#define S3_BH_O  38400
#define S3_BL_O  49920
#define S3_STG   61440
#define S3_SM    (3 * S3_STG)     // 184320

__global__ void __launch_bounds__(256) stage3_mma(
    const float* __restrict__ fuse_b, float* __restrict__ out)
{
    extern __shared__ __align__(16) char sm[];
    const uint32_t sbase = smem_u32(sm);
    const int h0  = blockIdx.x * 2;
    const int coh = blockIdx.y;
    const int n   = blockIdx.z;
    const int tid = threadIdx.x;
    const int warp = tid >> 5, lane = tid & 31;
    const int g = lane >> 2, t = lane & 3;
    const int r  = warp & 1;
    const int wm = (warp >> 1) & 1;
    const int wn = warp >> 2;
    const int rsel = lane & 15;
    const int half16 = (lane >> 4) * 16;

    auto prefetch = [&](int chunk, uint32_t so) {
        if (tid < 196) {
            const int rh = tid / 98;
            const int u  = tid - rh * 98;
            const int w  = u - 1;
            const bool wok = (unsigned)w < (unsigned)WW;
#pragma unroll
            for (int rr = 0; rr < 16; rr++) {
                int row = rh * 16 + rr;
                int dy = row >> 3, kpl = row & 7;
                int hh = h0 + dy - 1;
                uint32_t sz = (wok && (unsigned)hh < (unsigned)HH) ? 4u : 0u;
                size_t gi = ((size_t)n * 128 + chunk * 8 + kpl) * PP
                            + (sz ? (hh * WW + w) : 0);
                uint32_t doff = sbase + so + (uint32_t)(((dy * 100 + u) * 12 + kpl) * 4);
                cp4z(doff,           g_ch + gi, sz);
                cp4z(doff + S3_AL_O, g_cl + gi, sz);
            }
        }
#pragma unroll
        for (int ps = 0; ps < 3; ps++) {
            int fid = tid + ps * 256;
            if (fid < 576) {
                int tapk = fid >> 3, q = fid & 7;
                size_t gi = ((size_t)chunk * 72 + tapk) * 64 + coh * 32 + q * 4;
                uint32_t doff = sbase + so + S3_BH_O + (uint32_t)((tapk * 40 + q * 4) * 4);
                cp16(doff,                       g_wBh + gi);
                cp16(doff + (S3_BL_O - S3_BH_O), g_wBl + gi);
            }
        }
        asm volatile("cp.async.commit_group;" ::: "memory");
    };

    // 3 accumulator sets, one per split
    float d[3][3][2][4];
#pragma unroll
    for (int s = 0; s < 3; s++)
#pragma unroll
        for (int i = 0; i < 3; i++)
#pragma unroll
            for (int j = 0; j < 2; j++)
#pragma unroll
                for (int q = 0; q < 4; q++) d[s][i][j][q] = 0.f;

    prefetch(0, 0);

    int cur = 0;
#pragma unroll 1
    for (int chunk = 0; chunk < 16; chunk++) {
        const uint32_t so = (uint32_t)cur * S3_STG;
        int nxt = (cur == 2) ? 0 : cur + 1;
        if (chunk + 1 < 16) {
            prefetch(chunk + 1, (uint32_t)nxt * S3_STG);
            asm volatile("cp.async.wait_group 1;" ::: "memory");
        } else {
            asm volatile("cp.async.wait_group 0;" ::: "memory");
        }
        __syncthreads();

        const uint32_t AbH = sbase + so + rsel * 48 + half16;
        const uint32_t AbL = AbH + S3_AL_O;
        const char* BpH = sm + so + S3_BH_O;
        const char* BpL = sm + so + S3_BL_O;

#pragma unroll
        for (int tap = 0; tap < 9; tap++) {
            const int dy = tap / 3, dx = tap % 3;
            uint32_t bH[2][2], bL[2][2];
#pragma unroll
            for (int ni = 0; ni < 2; ni++) {
                int coL = wn * 16 + ni * 8 + g;
                bH[ni][0] = *(const uint32_t*)(BpH + ((tap * 8 + t) * 40 + coL) * 4);
                bH[ni][1] = *(const uint32_t*)(BpH + ((tap * 8 + t + 4) * 40 + coL) * 4);
                bL[ni][0] = *(const uint32_t*)(BpL + ((tap * 8 + t) * 40 + coL) * 4);
                bL[ni][1] = *(const uint32_t*)(BpL + ((tap * 8 + t + 4) * 40 + coL) * 4);
            }
            uint32_t aH[3][4], aL[3][4];
#pragma unroll
            for (int mi = 0; mi < 3; mi++) {
                int px0 = wm * 48 + mi * 16 + dx;
                int off = ((r + dy) * 100 + px0) * 48;
                ldsm_x4(aH[mi][0], aH[mi][1], aH[mi][2], aH[mi][3], AbH + off);
                ldsm_x4(aL[mi][0], aL[mi][1], aL[mi][2], aL[mi][3], AbL + off);
            }
            // 18 MMAs, each accumulator touched once per tap (distance 18)
#pragma unroll
            for (int s = 0; s < 3; s++)
#pragma unroll
                for (int mi = 0; mi < 3; mi++)
#pragma unroll
                    for (int ni = 0; ni < 2; ni++) {
                        const uint32_t* a = (s < 2) ? aH[mi] : aL[mi];
                        const uint32_t* b = (s == 1) ? bL[ni] : bH[ni];
                        mma16816(d[s][mi][ni][0], d[s][mi][ni][1],
                                 d[s][mi][ni][2], d[s][mi][ni][3],
                                 a[0], a[1], a[2], a[3], b[0], b[1]);
                    }
        }
        cur = nxt;
    }

    const int h = h0 + r;
#pragma unroll
    for (int mi = 0; mi < 3; mi++) {
        int pxcol = wm * 48 + mi * 16 + g;
#pragma unroll
        for (int ni = 0; ni < 2; ni++) {
            int co = coh * 32 + wn * 16 + ni * 8 + 2 * t;
            float b0v = __ldg(fuse_b + co);
            float b1v = __ldg(fuse_b + co + 1);
            float* r0 = out + ((size_t)n * CC + co) * PP + h * WW;
            float* r1 = r0 + PP;
            float v0 = d[0][mi][ni][0] + d[1][mi][ni][0] + d[2][mi][ni][0];
            float v1 = d[0][mi][ni][1] + d[1][mi][ni][1] + d[2][mi][ni][1];
            float v2 = d[0][mi][ni][2] + d[1][mi][ni][2] + d[2][mi][ni][2];
            float v3 = d[0][mi][ni][3] + d[1][mi][ni][3] + d[2][mi][ni][3];
            r0[pxcol]     = v0 + b0v;
            r1[pxcol]     = v1 + b1v;
            r0[pxcol + 8] = v2 + b0v;
            r1[pxcol + 8] = v3 + b1v;
        }
    }
}

// ============================================================
extern "C" void kernel_launch(void* const* d_in, const int* in_sizes, int n_in,
                              void* d_out, int out_size)
{
    (void)in_sizes; (void)n_in; (void)out_size;
    const float* x      = (const float*)d_in[0];
    const float* y      = (const float*)d_in[1];
    const float* gen_w  = (const float*)d_in[2];
    const float* gen_b  = (const float*)d_in[3];
    const float* fuse_w = (const float*)d_in[4];
    const float* fuse_b = (const float*)d_in[5];
    float* out = (float*)d_out;

    cudaFuncSetAttribute(fused12, cudaFuncAttributeMaxDynamicSharedMemorySize, F_SM);
    cudaFuncSetAttribute(stage3_mma, cudaFuncAttributeMaxDynamicSharedMemorySize, S3_SM);

    prep_all<<<504, 256>>>(gen_w, gen_b, fuse_w);

    fused12<<<dim3(PP / 128, NN), 256, F_SM>>>(x, y);

    stage3_mma<<<dim3(HH / 2, 2, NN), 256, S3_SM>>>(fuse_b, out);
}